// round 16
// baseline (speedup 1.0000x reference)
#include <cuda_runtime.h>
#include <math.h>

#define NMOL 256
#define NPER 32
#define NNODE 8192
#define EPM 992
#define ETOT (NMOL*EPM)
#define SD 256
#define ED 32
#define MSG_IN 546
#define MSG_OUT 353
#define NT 512
#define HROWS 16

typedef unsigned long long u64;

// global scratch (sanctioned __device__ arrays)
__device__ float g_e[(size_t)ETOT*ED];                  // edge features (32.5MB, L2)
__device__ __align__(16) float g_w2t [5*64*32*4];       // W2e transposed [l][c4][k][4]
__device__ __align__(16) float g_w1tA[5*8*128*4];       // W1c k-grouped, even cols
__device__ __align__(16) float g_w1tB[5*8*128*4];       // W1c k-grouped, odd cols
__device__ __align__(16) float g_Q [(size_t)NMOL*NPER*SD];
__device__ __align__(16) float g_P [(size_t)NMOL*NPER*SD];
__device__ __align__(16) float g_S0[(size_t)NMOL*NPER*SD];
__device__ __align__(16) float g_s [(size_t)NMOL*NPER*SD];

struct SM {
    float w1sA[8*128*4];       // 16KB  [B] weights even cols (staged per layer)
    float w1sB[8*128*4];       // 16KB  [B] weights odd cols
    float hdn [2][NPER][SD];   // 64KB (j0/j1)
    float dT  [NPER][NPER];    // 4KB   d[j][i] per layer
    float aT  [NPER][NPER];    // 4KB   a[j][i] per layer
    float w2p [SD];            // 1KB
    float pos [NPER][3];
    float npos[NPER][3];
    float pdpart[2][2][16][3]; // [parity][jb][warp][xyz]
};

__device__ __forceinline__ float silu_f(float v){
    return v * (1.0f / (1.0f + __expf(-v)));
}
__device__ __forceinline__ void unpack2(u64 v, float& x, float& y){
    asm("mov.b64 {%0, %1}, %2;" : "=f"(x), "=f"(y) : "l"(v));
}
__device__ __forceinline__ u64 fma2(u64 a, u64 b, u64 c){
    u64 d; asm("fma.rn.f32x2 %0, %1, %2, %3;" : "=l"(d) : "l"(a), "l"(b), "l"(c)); return d;
}

// prep: weight permutations
__global__ void prep_kernel(const float* __restrict__ gW2, const float* __restrict__ gW1){
    int idx = blockIdx.x*256 + threadIdx.x;
    if (idx < 5*8192){
        int l = idx >> 13; int rem = idx & 8191;
        int c4 = rem >> 7; int rem2 = rem & 127;
        int k = rem2 >> 2; int cc = rem2 & 3;
        g_w2t[idx] = gW2[((size_t)l*256 + 4*c4 + cc)*MSG_OUT + 321 + k];
        return;
    }
    idx -= 5*8192;
    if (idx < 2*5*4096){
        int half = idx / (5*4096);
        int r = idx % (5*4096);
        int l = r >> 12; int q = r & 4095;
        int g = q >> 9; int pp = (q >> 2) & 127; int kk = q & 3;
        float v = gW1[((size_t)l*MSG_IN + 512 + 4*g + kk)*SD + 2*pp + half];
        if (half == 0) g_w1tA[l*4096 + q] = v;
        else           g_w1tB[l*4096 + q] = v;
    }
}

__global__ void __launch_bounds__(NT,2) dec_kernel(
    const float* __restrict__ x,   const float* __restrict__ z,
    const float* __restrict__ rot, const float* __restrict__ eattr,
    const float* __restrict__ Wam, const float* __restrict__ bam,
    const float* __restrict__ Wbm, const float* __restrict__ bbm,
    const float* __restrict__ gW1, const float* __restrict__ gb1,
    const float* __restrict__ gW2, const float* __restrict__ gb2,
    const float* __restrict__ Wh1, const float* __restrict__ bh1,
    const float* __restrict__ Wh2, const float* __restrict__ bh2,
    const float* __restrict__ We1, const float* __restrict__ be1,
    const float* __restrict__ We2, const float* __restrict__ be2,
    float* __restrict__ outA, float* __restrict__ outB, float* __restrict__ outP)
{
    extern __shared__ float smraw[];
    SM* sm = (SM*)smraw;
    const int tid  = threadIdx.x;
    const int lane = tid & 31;
    const int wrp  = tid >> 5;
    const int mol  = blockIdx.x;
    const int nodeBase = mol * NPER;
    const size_t ebase = (size_t)mol * EPM;
    const int c  = tid & 255;
    const int r0 = (tid >> 8) * HROWS;
    const int p  = tid & 127;         // col-pair (2p,2p+1) in [B]
    const int rq = (tid >> 7) * 8;    // row quarter start in [B]
    float* Qg  = g_Q  + (size_t)mol*NPER*SD;
    float* Pg  = g_P  + (size_t)mol*NPER*SD;
    float* S0g = g_S0 + (size_t)mol*NPER*SD;
    float* sg  = g_s  + (size_t)mol*NPER*SD;

    // ---------------- Embed ----------------
    {
        float* xz = &sm->hdn[0][0][0];
        for (int idx = tid; idx < NPER*80; idx += NT){
            int i = idx / 80, k = idx % 80;
            xz[idx] = (k < 16) ? x[(nodeBase+i)*16 + k] : z[(nodeBase+i)*64 + (k-16)];
        }
        __syncthreads();
        float acc[HROWS];
#pragma unroll
        for (int r=0;r<HROWS;r++) acc[r]=0.f;
        for (int kg=0; kg<20; kg++){
            float w0=Wam[(4*kg+0)*259+c], w1=Wam[(4*kg+1)*259+c];
            float w2v=Wam[(4*kg+2)*259+c], w3=Wam[(4*kg+3)*259+c];
#pragma unroll
            for (int r=0;r<HROWS;r++){
                float4 v = ((const float4*)xz)[(r0+r)*20+kg];
                acc[r] += v.x*w0 + v.y*w1 + v.z*w2v + v.w*w3;
            }
        }
        float b = bam[c];
#pragma unroll
        for (int r=0;r<HROWS;r++) sg[(r0+r)*SD + c] = acc[r] + b;
        if (tid < 96){
            int i = tid/3, cc = tid%3;
            float a = bam[256+cc];
            for (int k=0;k<80;k++) a += xz[i*80+k]*Wam[k*259+256+cc];
            sm->npos[i][cc] = a;
        }
        __syncthreads();
        if (tid < 96){
            int i = tid/3, cc = tid%3;
            float pv = 0.f;
#pragma unroll
            for (int q=0;q<3;q++) pv += rot[mol*9 + cc*3 + q]*sm->npos[i][q];
            sm->pos[i][cc] = pv;
        }
    }

    // ---------------- e init ----------------
    for (int idx = tid; idx < EPM*ED; idx += NT){
        int eL = idx >> 5, k = idx & 31;
        const float* ea = &eattr[(ebase+eL)*5];
        float a = bbm[k];
#pragma unroll
        for (int q=0;q<5;q++) a += ea[q]*Wbm[q*ED+k];
        g_e[(ebase+eL)*ED + k] = a;
    }
    __syncthreads();

    // ---------------- 5 layers ----------------
    for (int l=0; l<5; l++){
        const float* W1 = gW1 + (size_t)l*MSG_IN*SD;
        const float* b1 = gb1 + l*SD;
        const float* W2 = gW2 + (size_t)l*SD*MSG_OUT;
        const float* b2 = gb2 + l*MSG_OUT;

        if (tid < 256) sm->w2p[tid] = W2[tid*MSG_OUT + 320];
        if (tid < 96) sm->npos[tid/3][tid%3] = 0.f;

        // stage w1 weights into SMEM
        {
            const float4* sa = (const float4*)(g_w1tA + l*4096);
            const float4* sb = (const float4*)(g_w1tB + l*4096);
            float4* da = (float4*)sm->w1sA; float4* db = (float4*)sm->w1sB;
            for (int idx = tid; idx < 1024; idx += NT){ da[idx]=sa[idx]; db[idx]=sb[idx]; }
        }
        // geometry tables (pos is layer-invariant)
        for (int idx = tid; idx < NPER*NPER; idx += NT){
            int j = idx >> 5, i = idx & 31;
            float pix=sm->pos[i][0], piy=sm->pos[i][1], piz=sm->pos[i][2];
            float pjx=sm->pos[j][0], pjy=sm->pos[j][1], pjz=sm->pos[j][2];
            float rx=pjx-pix, ry=pjy-piy, rz=pjz-piz;
            float d = sqrtf(fmaxf(rx*rx+ry*ry+rz*rz, 1e-6f));
            sm->dT[j][i] = d;
            sm->aT[j][i] = pix*pjx+piy*pjy+piz*pjz;
        }

        // P = s@W1a -> global
        {
            float acc[HROWS];
#pragma unroll
            for (int r=0;r<HROWS;r++) acc[r]=0.f;
            for (int kg=0; kg<64; kg++){
                float wa0=W1[(4*kg+0)*SD+c], wa1=W1[(4*kg+1)*SD+c];
                float wa2=W1[(4*kg+2)*SD+c], wa3=W1[(4*kg+3)*SD+c];
#pragma unroll
                for (int r=0;r<HROWS;r++){
                    const float4 v = __ldg((const float4*)&sg[(r0+r)*SD + 4*kg]);
                    acc[r] += v.x*wa0 + v.y*wa1 + v.z*wa2 + v.w*wa3;
                }
            }
#pragma unroll
            for (int r=0;r<HROWS;r++) Pg[(r0+r)*SD + c]=acc[r];
        }
        // Q = s@W1b + b1 -> global
        {
            float acc[HROWS];
#pragma unroll
            for (int r=0;r<HROWS;r++) acc[r]=0.f;
            for (int kg=0; kg<64; kg++){
                float wb0=W1[(256+4*kg+0)*SD+c], wb1=W1[(256+4*kg+1)*SD+c];
                float wb2=W1[(256+4*kg+2)*SD+c], wb3=W1[(256+4*kg+3)*SD+c];
#pragma unroll
                for (int r=0;r<HROWS;r++){
                    const float4 v = __ldg((const float4*)&sg[(r0+r)*SD + 4*kg]);
                    acc[r] += v.x*wb0 + v.y*wb1 + v.z*wb2 + v.w*wb3;
                }
            }
            float bb = b1[c];
#pragma unroll
            for (int r=0;r<HROWS;r++) Qg[(r0+r)*SD + c] = acc[r]+bb;
        }
        __syncthreads();

        const float w1dx = __ldg(&W1[544*SD + 2*p]);
        const float w1dy = __ldg(&W1[544*SD + 2*p+1]);
        const float w1ex = __ldg(&W1[545*SD + 2*p]);
        const float w1ey = __ldg(&W1[545*SD + 2*p+1]);
        const float b2p  = __ldg(&b2[320]);
        const float b2k  = __ldg(&b2[321+lane]);

        for (int jp=0; jp<16; jp++){
            const int j0 = 2*jp;
            const int buf = jp & 1, nbuf = buf ^ 1;

            // ---- [B]: hdn for j0 then j1; e rows read directly from g_e ----
            {
                u64 pv[8];
#pragma unroll
                for (int r=0;r<8;r++) pv[r] = __ldg((const u64*)&Pg[(rq+r)*SD + 2*p]);
#pragma unroll 1
                for (int jb=0; jb<2; jb++){
                    const int j = j0 + jb;
                    const u64 qv = __ldg((const u64*)&Qg[j*SD + 2*p]);
                    unsigned int eoff[8];
#pragma unroll
                    for (int r=0;r<8;r++){
                        int i = rq + r;
                        eoff[r] = (unsigned int)((ebase + i*31 + j - (j>i))*ED);
                    }
                    u64 acc0[8], acc1[8];
#pragma unroll
                    for (int r=0;r<8;r++){ acc0[r]=0ULL; acc1[r]=0ULL; }
#pragma unroll
                    for (int g=0;g<8;g++){
                        const ulonglong2 WA = *(const ulonglong2*)&sm->w1sA[(g*128+p)*4];
                        const ulonglong2 WB = *(const ulonglong2*)&sm->w1sB[(g*128+p)*4];
#pragma unroll
                        for (int r=0;r<8;r++){
                            const ulonglong2 E = *(const ulonglong2*)(g_e + eoff[r] + 4*g);
                            acc0[r]=fma2(E.x,WA.x,acc0[r]); acc0[r]=fma2(E.y,WA.y,acc0[r]);
                            acc1[r]=fma2(E.x,WB.x,acc1[r]); acc1[r]=fma2(E.y,WB.y,acc1[r]);
                        }
                    }
                    float qx,qy; unpack2(qv,qx,qy);
#pragma unroll
                    for (int r=0;r<8;r++){
                        int i = rq+r;
                        float d = sm->dT[j][i], a = sm->aT[j][i];
                        float px,py; unpack2(pv[r],px,py);
                        float a0x,a0y,a1x,a1y;
                        unpack2(acc0[r],a0x,a0y); unpack2(acc1[r],a1x,a1y);
                        float h0 = a0x+a0y + px + qx + d*w1dx + a*w1ex;
                        float h1 = a1x+a1y + py + qy + d*w1dy + a*w1ey;
                        h0 = silu_f(h0); h1 = silu_f(h1);
                        if (i==j){ h0=0.f; h1=0.f; }
                        *(float2*)&sm->hdn[jb][i][2*p] = make_float2(h0,h1);
                    }
                }
            }
            __syncthreads();

            // ---- [C]: C2 REDs + C1 + fold prev pdpart + C0 ----
            {
                // [C2]: warp = (quarter qq of columns) x (group of 16 streams)
                const int qq  = wrp >> 2;
                const int sub = wrp & 3;
                const float* wtq = g_w2t + l*8192 + lane*4;
                u64 acc[16];
#pragma unroll
                for (int m=0;m<16;m++) acc[m]=0ULL;
#pragma unroll 4
                for (int cc4=0; cc4<16; cc4++){
                    const int c4 = qq*16 + cc4;
                    const ulonglong2 ww = *(const ulonglong2*)&wtq[c4*128];
                    const float* hb = &sm->hdn[0][0][4*c4] + (size_t)sub*16*SD;
#pragma unroll
                    for (int m=0;m<16;m++){
                        const ulonglong2 hv = *(const ulonglong2*)(hb + m*SD);
                        acc[m]=fma2(hv.x,ww.x,acc[m]); acc[m]=fma2(hv.y,ww.y,acc[m]);
                    }
                }
#pragma unroll
                for (int m=0;m<16;m++){
                    int st = sub*16 + m;         // 0..63 = jb*32 + i
                    int jb = st >> 5, i = st & 31;
                    int j = j0 + jb;
                    if (i != j){
                        float ax,ay; unpack2(acc[m],ax,ay);
                        float val = ax + ay + (qq==0 ? b2k : 0.f);
                        int eL = i*31 + j - (j>i);
                        atomicAdd(&g_e[(ebase+eL)*ED + lane], val);
                    }
                }
            }
            // [C1] pos scalars (rn recomputed from pos/dT) -> pdpart[buf]
#pragma unroll
            for (int jb=0; jb<2; jb++){
                const int j = j0 + jb;
                float pdx=0.f, pdy=0.f, pdz=0.f;
#pragma unroll
                for (int r=0;r<2;r++){
                    int i = wrp + 16*r;
                    float part = 0.f;
#pragma unroll
                    for (int m=0;m<8;m++)
                        part += sm->hdn[jb][i][lane+32*m] * sm->w2p[lane+32*m];
#pragma unroll
                    for (int off=16; off>0; off>>=1)
                        part += __shfl_xor_sync(0xffffffffu, part, off);
                    if (lane==0 && i != j){
                        float t = part + b2p;
                        float d = sm->dT[j][i];
                        float inv = 1.f/(1.f+d);
                        float rx = sm->pos[j][0]-sm->pos[i][0];
                        float ry = sm->pos[j][1]-sm->pos[i][1];
                        float rz = sm->pos[j][2]-sm->pos[i][2];
                        pdx += rx*inv*t;
                        pdy += ry*inv*t;
                        pdz += rz*inv*t;
                    }
                }
                if (lane==0){
                    sm->pdpart[buf][jb][wrp][0]=pdx;
                    sm->pdpart[buf][jb][wrp][1]=pdy;
                    sm->pdpart[buf][jb][wrp][2]=pdz;
                }
            }
            // fold previous jp's pdpart into npos
            if (jp>0 && tid<6){
                int sel = tid/3, cc = tid - sel*3;
                float sum=0.f;
#pragma unroll
                for (int w=0;w<16;w++) sum += sm->pdpart[nbuf][sel][w][cc];
                sm->npos[j0-2+sel][cc] += sum;
            }
            // [C0] S0 rows j0,j1 via column sums
            {
                int jb = tid >> 8;
                int col = tid & 255;
                float s0=0.f, s1=0.f;
#pragma unroll
                for (int i=0;i<32;i+=2){
                    s0 += sm->hdn[jb][i][col];
                    s1 += sm->hdn[jb][i+1][col];
                }
                S0g[(j0+jb)*SD + col] = s0 + s1;
            }
            __syncthreads();
        } // jp

        // fold last jp's pdpart (jp=15 -> buf=1)
        if (tid<6){
            int sel = tid/3, cc = tid - sel*3;
            float sum=0.f;
#pragma unroll
            for (int w=0;w<16;w++) sum += sm->pdpart[1][sel][w][cc];
            sm->npos[30+sel][cc] += sum;
        }
        // s += (S0 @ W2s)/31 + b2s
        {
            float acc[HROWS];
#pragma unroll
            for (int r=0;r<HROWS;r++) acc[r]=0.f;
            for (int kg=0; kg<64; kg++){
                float w0=W2[(4*kg+0)*MSG_OUT+c], w1=W2[(4*kg+1)*MSG_OUT+c];
                float w2v=W2[(4*kg+2)*MSG_OUT+c], w3=W2[(4*kg+3)*MSG_OUT+c];
#pragma unroll
                for (int r=0;r<HROWS;r++){
                    const float4 v = __ldg((const float4*)&S0g[(r0+r)*SD + 4*kg]);
                    acc[r] += v.x*w0 + v.y*w1 + v.z*w2v + v.w*w3;
                }
            }
            __syncthreads();  // npos folds done; buffers free
            float b2s = b2[c];
#pragma unroll
            for (int r=0;r<HROWS;r++)
                sg[(r0+r)*SD + c] += acc[r]*(1.f/31.f) + b2s;
        }
        if (tid<96){
            int i = tid/3, cc = tid%3;
            sm->pos[i][cc] += sm->npos[i][cc]*(1.f/31.f);
        }
        __syncthreads();
    } // layers

    // ---------------- atoms + pos out ----------------
    float* Pbuf = sm->w1sA;              // 32KB scratch (w1sA+w1sB contiguous)
    {
        float acc[HROWS];
#pragma unroll
        for (int r=0;r<HROWS;r++) acc[r]=0.f;
        for (int kg=0; kg<64; kg++){
            float w0=Wh1[(4*kg+0)*SD+c], w1=Wh1[(4*kg+1)*SD+c];
            float w2v=Wh1[(4*kg+2)*SD+c], w3=Wh1[(4*kg+3)*SD+c];
#pragma unroll
            for (int r=0;r<HROWS;r++){
                const float4 v = __ldg((const float4*)&sg[(r0+r)*SD + 4*kg]);
                acc[r] += v.x*w0 + v.y*w1 + v.z*w2v + v.w*w3;
            }
        }
        float bb = bh1[c];
#pragma unroll
        for (int r=0;r<HROWS;r++) Pbuf[(r0+r)*SD + c] = silu_f(acc[r]+bb);
    }
    __syncthreads();
    for (int o = tid; o < NPER*16; o += NT){
        int i = o>>4, cc = o&15;
        float a = bh2[cc];
        for (int k=0;k<SD;k++) a += Pbuf[i*SD + k]*Wh2[k*16+cc];
        outA[(nodeBase+i)*16+cc] = a;
    }
    if (tid < 96){
        int i = tid/3, cc = tid%3;
        outP[(nodeBase+i)*3+cc] = sm->pos[i][cc];
    }
    __syncthreads();

    // ---------------- bonds ----------------
    float* hdnf = &sm->hdn[0][0][0];
    float* bP = hdnf;                    // 32 x 128
    {
        const int c128 = tid & 127;
        const int grp  = tid >> 7;
        float acc[8];
#pragma unroll
        for (int r=0;r<8;r++) acc[r]=0.f;
        for (int kg=0; kg<64; kg++){
            float w0=We1[(4*kg+0)*128+c128], w1=We1[(4*kg+1)*128+c128];
            float w2v=We1[(4*kg+2)*128+c128], w3=We1[(4*kg+3)*128+c128];
#pragma unroll
            for (int r=0;r<8;r++){
                const float4 v = __ldg((const float4*)&sg[(grp*8+r)*SD + 4*kg]);
                acc[r] += v.x*w0 + v.y*w1 + v.z*w2v + v.w*w3;
            }
        }
#pragma unroll
        for (int r=0;r<8;r++) bP[(grp*8+r)*128 + c128] = acc[r];
    }
    float* We1e_s = hdnf + 16*SD;        // 32 x 128
    for (int idx = tid; idx < 32*128; idx += NT)
        We1e_s[idx] = We1[(256 + (idx>>7))*128 + (idx&127)];
    __syncthreads();

    float* bh = &sm->hdn[1][0][0];       // 16 x 128
    float* ebuf = &sm->dT[0][0];         // 16 x 32 scratch
    float* dloc = &sm->aT[0][0];         // 16 floats scratch
    {
        const int c128 = tid & 127;
        const int grp  = tid >> 7;
        const float w288 = We1[288*128 + c128];
        const float bbe  = be1[c128];
        for (int pblk=0; pblk<62; pblk++){
            for (int idx = tid; idx < 16*ED; idx += NT){
                int q = idx>>5, k = idx&31;
                int eL = pblk*16 + q;
                ebuf[q*32+k] = g_e[(ebase+eL)*ED + k];
            }
            if (tid < 16){
                int eL = pblk*16 + tid;
                int i = eL/31, jj = eL - i*31; int j = jj + (jj>=i);
                float rx=sm->pos[j][0]-sm->pos[i][0];
                float ry=sm->pos[j][1]-sm->pos[i][1];
                float rz=sm->pos[j][2]-sm->pos[i][2];
                dloc[tid] = sqrtf(fmaxf(rx*rx+ry*ry+rz*rz, 1e-6f));
            }
            __syncthreads();
#pragma unroll
            for (int qq=0; qq<4; qq++){
                int q = grp*4 + qq;
                int eL = pblk*16 + q;
                int i = eL/31, jj = eL - i*31; int j = jj + (jj>=i);
                float a = bbe + bP[i*128+c128] + bP[j*128+c128] + dloc[q]*w288;
#pragma unroll
                for (int kg=0; kg<8; kg++){
                    float4 e4 = ((const float4*)&ebuf[q*32])[kg];
                    a += e4.x*We1e_s[(4*kg+0)*128+c128] + e4.y*We1e_s[(4*kg+1)*128+c128]
                       + e4.z*We1e_s[(4*kg+2)*128+c128] + e4.w*We1e_s[(4*kg+3)*128+c128];
                }
                bh[q*128+c128] = silu_f(a);
            }
            __syncthreads();
            {
                int qq = wrp;
                int eL = pblk*16 + qq;
#pragma unroll
                for (int b=0;b<5;b++){
                    float part = 0.f;
#pragma unroll
                    for (int m=0;m<4;m++){
                        int cc = lane + 32*m;
                        part += bh[qq*128+cc] * We2[cc*5+b];
                    }
#pragma unroll
                    for (int off=16; off>0; off>>=1)
                        part += __shfl_xor_sync(0xffffffffu, part, off);
                    if (lane==0) outB[(ebase+eL)*5+b] = part + be2[b];
                }
            }
            __syncthreads();
        }
    }
}

extern "C" void kernel_launch(void* const* d_in, const int* in_sizes, int n_in,
                              void* d_out, int out_size)
{
    const float* x    = (const float*)d_in[0];
    const float* z    = (const float*)d_in[1];
    const float* rot  = (const float*)d_in[2];
    const float* eattr= (const float*)d_in[4];
    const float* Wam  = (const float*)d_in[6];
    const float* bam  = (const float*)d_in[7];
    const float* Wbm  = (const float*)d_in[8];
    const float* bbm  = (const float*)d_in[9];
    const float* gW1  = (const float*)d_in[10];
    const float* gb1  = (const float*)d_in[11];
    const float* gW2  = (const float*)d_in[12];
    const float* gb2  = (const float*)d_in[13];
    const float* Wh1  = (const float*)d_in[14];
    const float* bh1  = (const float*)d_in[15];
    const float* Wh2  = (const float*)d_in[16];
    const float* bh2  = (const float*)d_in[17];
    const float* We1  = (const float*)d_in[18];
    const float* be1  = (const float*)d_in[19];
    const float* We2  = (const float*)d_in[20];
    const float* be2  = (const float*)d_in[21];

    float* out  = (float*)d_out;
    float* outA = out;
    float* outB = out + (size_t)NNODE*16;
    float* outP = out + (size_t)NNODE*16 + (size_t)ETOT*5;

    prep_kernel<<<320, 256>>>(gW2, gW1);

    const size_t shmem = sizeof(SM);
    cudaFuncSetAttribute(dec_kernel, cudaFuncAttributeMaxDynamicSharedMemorySize, (int)shmem);
    dec_kernel<<<NMOL, NT, shmem>>>(x,z,rot,eattr,Wam,bam,Wbm,bbm,
                                    gW1,gb1,gW2,gb2,Wh1,bh1,Wh2,bh2,
                                    We1,be1,We2,be2,outA,outB,outP);
}

// round 17
// speedup vs baseline: 1.2790x; 1.2790x over previous
#include <cuda_runtime.h>
#include <math.h>

#define NMOL 256
#define NPER 32
#define NNODE 8192
#define EPM 992
#define ETOT (NMOL*EPM)
#define SD 256
#define ED 32
#define MSG_IN 546
#define MSG_OUT 353
#define NT 512
#define HROWS 16

typedef unsigned long long u64;

// global scratch (sanctioned __device__ arrays)
__device__ __align__(16) float g_e[(size_t)ETOT*ED];    // edge features (32.5MB, L2)
__device__ __align__(16) float g_w2t [5*64*32*4];       // W2e transposed [l][c4][k][4]
__device__ __align__(16) float g_w1tA[5*8*128*4];       // W1c k-grouped, even cols
__device__ __align__(16) float g_w1tB[5*8*128*4];       // W1c k-grouped, odd cols
__device__ __align__(16) float g_Q [(size_t)NMOL*NPER*SD];
__device__ __align__(16) float g_P [(size_t)NMOL*NPER*SD];
__device__ __align__(16) float g_S0[(size_t)NMOL*NPER*SD];
__device__ __align__(16) float g_s [(size_t)NMOL*NPER*SD];

struct SM {
    float w1sA[8*128*4];       // 16KB  [B] weights even cols (staged per layer)
    float w1sB[8*128*4];       // 16KB  [B] weights odd cols
    float hdn [2][NPER][SD];   // 64KB (j0/j1)
    float esm [2][NPER][ED];   // 8KB non-dup e rows for j0/j1
    float w2p [SD];            // 1KB
    float pos [NPER][3];
    float npos[NPER][3];
    float dbuf[2][NPER];
    float abuf[2][NPER];
    float rnb [2][NPER][3];
    float pdpart[2][16][3];
};

__device__ __forceinline__ float silu_f(float v){
    return v * (1.0f / (1.0f + __expf(-v)));
}
__device__ __forceinline__ void unpack2(u64 v, float& x, float& y){
    asm("mov.b64 {%0, %1}, %2;" : "=f"(x), "=f"(y) : "l"(v));
}
__device__ __forceinline__ u64 fma2(u64 a, u64 b, u64 c){
    u64 d; asm("fma.rn.f32x2 %0, %1, %2, %3;" : "=l"(d) : "l"(a), "l"(b), "l"(c)); return d;
}

// prep: weight permutations
__global__ void prep_kernel(const float* __restrict__ gW2, const float* __restrict__ gW1){
    int idx = blockIdx.x*256 + threadIdx.x;
    if (idx < 5*8192){
        int l = idx >> 13; int rem = idx & 8191;
        int c4 = rem >> 7; int rem2 = rem & 127;
        int k = rem2 >> 2; int cc = rem2 & 3;
        g_w2t[idx] = gW2[((size_t)l*256 + 4*c4 + cc)*MSG_OUT + 321 + k];
        return;
    }
    idx -= 5*8192;
    if (idx < 2*5*4096){
        int half = idx / (5*4096);
        int r = idx % (5*4096);
        int l = r >> 12; int q = r & 4095;
        int g = q >> 9; int pp = (q >> 2) & 127; int kk = q & 3;
        float v = gW1[((size_t)l*MSG_IN + 512 + 4*g + kk)*SD + 2*pp + half];
        if (half == 0) g_w1tA[l*4096 + q] = v;
        else           g_w1tB[l*4096 + q] = v;
    }
}

__global__ void __launch_bounds__(NT,2) dec_kernel(
    const float* __restrict__ x,   const float* __restrict__ z,
    const float* __restrict__ rot, const float* __restrict__ eattr,
    const float* __restrict__ Wam, const float* __restrict__ bam,
    const float* __restrict__ Wbm, const float* __restrict__ bbm,
    const float* __restrict__ gW1, const float* __restrict__ gb1,
    const float* __restrict__ gW2, const float* __restrict__ gb2,
    const float* __restrict__ Wh1, const float* __restrict__ bh1,
    const float* __restrict__ Wh2, const float* __restrict__ bh2,
    const float* __restrict__ We1, const float* __restrict__ be1,
    const float* __restrict__ We2, const float* __restrict__ be2,
    float* __restrict__ outA, float* __restrict__ outB, float* __restrict__ outP)
{
    extern __shared__ float smraw[];
    SM* sm = (SM*)smraw;
    const int tid  = threadIdx.x;
    const int lane = tid & 31;
    const int wrp  = tid >> 5;
    const int mol  = blockIdx.x;
    const int nodeBase = mol * NPER;
    const size_t ebase = (size_t)mol * EPM;
    const int c  = tid & 255;
    const int r0 = (tid >> 8) * HROWS;
    const int p  = tid & 127;         // col-pair (2p,2p+1) in [B]
    const int rq = (tid >> 7) * 8;    // row quarter start in [B]
    float* Qg  = g_Q  + (size_t)mol*NPER*SD;
    float* Pg  = g_P  + (size_t)mol*NPER*SD;
    float* S0g = g_S0 + (size_t)mol*NPER*SD;
    float* sg  = g_s  + (size_t)mol*NPER*SD;

    // ---------------- Embed ----------------
    {
        float* xz = &sm->hdn[0][0][0];
        for (int idx = tid; idx < NPER*80; idx += NT){
            int i = idx / 80, k = idx % 80;
            xz[idx] = (k < 16) ? x[(nodeBase+i)*16 + k] : z[(nodeBase+i)*64 + (k-16)];
        }
        __syncthreads();
        float acc[HROWS];
#pragma unroll
        for (int r=0;r<HROWS;r++) acc[r]=0.f;
        for (int kg=0; kg<20; kg++){
            float w0=Wam[(4*kg+0)*259+c], w1=Wam[(4*kg+1)*259+c];
            float w2v=Wam[(4*kg+2)*259+c], w3=Wam[(4*kg+3)*259+c];
#pragma unroll
            for (int r=0;r<HROWS;r++){
                float4 v = ((const float4*)xz)[(r0+r)*20+kg];
                acc[r] += v.x*w0 + v.y*w1 + v.z*w2v + v.w*w3;
            }
        }
        float b = bam[c];
#pragma unroll
        for (int r=0;r<HROWS;r++) sg[(r0+r)*SD + c] = acc[r] + b;
        if (tid < 96){
            int i = tid/3, cc = tid%3;
            float a = bam[256+cc];
            for (int k=0;k<80;k++) a += xz[i*80+k]*Wam[k*259+256+cc];
            sm->npos[i][cc] = a;
        }
        __syncthreads();
        if (tid < 96){
            int i = tid/3, cc = tid%3;
            float pv = 0.f;
#pragma unroll
            for (int q=0;q<3;q++) pv += rot[mol*9 + cc*3 + q]*sm->npos[i][q];
            sm->pos[i][cc] = pv;
        }
    }

    // ---------------- e init ----------------
    for (int idx = tid; idx < EPM*ED; idx += NT){
        int eL = idx >> 5, k = idx & 31;
        const float* ea = &eattr[(ebase+eL)*5];
        float a = bbm[k];
#pragma unroll
        for (int q=0;q<5;q++) a += ea[q]*Wbm[q*ED+k];
        g_e[(ebase+eL)*ED + k] = a;
    }
    __syncthreads();

    // ---------------- 5 layers ----------------
    for (int l=0; l<5; l++){
        const float* W1 = gW1 + (size_t)l*MSG_IN*SD;
        const float* b1 = gb1 + l*SD;
        const float* W2 = gW2 + (size_t)l*SD*MSG_OUT;
        const float* b2 = gb2 + l*MSG_OUT;

        if (tid < 256) sm->w2p[tid] = W2[tid*MSG_OUT + 320];
        if (tid < 96) sm->npos[tid/3][tid%3] = 0.f;

        // stage w1 weights into SMEM
        {
            const float4* sa = (const float4*)(g_w1tA + l*4096);
            const float4* sb = (const float4*)(g_w1tB + l*4096);
            float4* da = (float4*)sm->w1sA; float4* db = (float4*)sm->w1sB;
            for (int idx = tid; idx < 1024; idx += NT){ da[idx]=sa[idx]; db[idx]=sb[idx]; }
        }

        // P = s@W1a -> global
        {
            float acc[HROWS];
#pragma unroll
            for (int r=0;r<HROWS;r++) acc[r]=0.f;
            for (int kg=0; kg<64; kg++){
                float wa0=W1[(4*kg+0)*SD+c], wa1=W1[(4*kg+1)*SD+c];
                float wa2=W1[(4*kg+2)*SD+c], wa3=W1[(4*kg+3)*SD+c];
#pragma unroll
                for (int r=0;r<HROWS;r++){
                    const float4 v = __ldg((const float4*)&sg[(r0+r)*SD + 4*kg]);
                    acc[r] += v.x*wa0 + v.y*wa1 + v.z*wa2 + v.w*wa3;
                }
            }
#pragma unroll
            for (int r=0;r<HROWS;r++) Pg[(r0+r)*SD + c]=acc[r];
        }
        // Q = s@W1b + b1 -> global
        {
            float acc[HROWS];
#pragma unroll
            for (int r=0;r<HROWS;r++) acc[r]=0.f;
            for (int kg=0; kg<64; kg++){
                float wb0=W1[(256+4*kg+0)*SD+c], wb1=W1[(256+4*kg+1)*SD+c];
                float wb2=W1[(256+4*kg+2)*SD+c], wb3=W1[(256+4*kg+3)*SD+c];
#pragma unroll
                for (int r=0;r<HROWS;r++){
                    const float4 v = __ldg((const float4*)&sg[(r0+r)*SD + 4*kg]);
                    acc[r] += v.x*wb0 + v.y*wb1 + v.z*wb2 + v.w*wb3;
                }
            }
            float bb = b1[c];
#pragma unroll
            for (int r=0;r<HROWS;r++) Qg[(r0+r)*SD + c] = acc[r]+bb;
        }
        __syncthreads();

        const float w1dx = __ldg(&W1[544*SD + 2*p]);
        const float w1dy = __ldg(&W1[544*SD + 2*p+1]);
        const float w1ex = __ldg(&W1[545*SD + 2*p]);
        const float w1ey = __ldg(&W1[545*SD + 2*p+1]);
        const float b2p  = __ldg(&b2[320]);
        const float b2k  = __ldg(&b2[321+lane]);

        for (int jp=0; jp<16; jp++){
            const int j0 = 2*jp;

            // ---- [A]: fold prev pdparts; stage e rows (one float4/thread) + geometry ----
            if (jp>0 && tid<6){
                int sel = tid/3, cc = tid - sel*3;
                float sum=0.f;
#pragma unroll
                for (int w=0;w<16;w++) sum += sm->pdpart[sel][w][cc];
                sm->npos[j0-2+sel][cc] += sum;
            }
            {   // 512 float4 = exactly NT threads: jb=tid>>8, i=(tid&255)>>3, k4=tid&7
                int jb = tid >> 8;
                int i  = (tid & 255) >> 3;
                int k4 = tid & 7;
                int j  = j0 + jb;
                float4 v = make_float4(0.f,0.f,0.f,0.f);
                if (i != j)
                    v = *(const float4*)&g_e[(ebase + i*31 + j - (j>i))*ED + 4*k4];
                *(float4*)&sm->esm[jb][i][4*k4] = v;
            }
            if (tid < 64){
                int jb = tid>>5, i = tid&31, j = j0+jb;
                float pix=sm->pos[i][0], piy=sm->pos[i][1], piz=sm->pos[i][2];
                float pjx=sm->pos[j][0], pjy=sm->pos[j][1], pjz=sm->pos[j][2];
                float rx=pjx-pix, ry=pjy-piy, rz=pjz-piz;
                float d = sqrtf(fmaxf(rx*rx+ry*ry+rz*rz, 1e-6f));
                float inv = 1.f/(1.f+d);
                sm->dbuf[jb][i]=d; sm->abuf[jb][i]=pix*pjx+piy*pjy+piz*pjz;
                if (i==j){rx=0;ry=0;rz=0;}
                sm->rnb[jb][i][0]=rx*inv; sm->rnb[jb][i][1]=ry*inv; sm->rnb[jb][i][2]=rz*inv;
            }
            __syncthreads();

            // ---- [B]: hdn for j0 then j1 (P hoisted once per jp; SMEM weights) ----
            {
                u64 pv[8];
#pragma unroll
                for (int r=0;r<8;r++) pv[r] = __ldg((const u64*)&Pg[(rq+r)*SD + 2*p]);
#pragma unroll 1
                for (int jb=0; jb<2; jb++){
                    const int j = j0 + jb;
                    const u64 qv = __ldg((const u64*)&Qg[j*SD + 2*p]);
                    u64 acc0[8], acc1[8];
#pragma unroll
                    for (int r=0;r<8;r++){ acc0[r]=0ULL; acc1[r]=0ULL; }
#pragma unroll
                    for (int g=0;g<8;g++){
                        const ulonglong2 WA = *(const ulonglong2*)&sm->w1sA[(g*128+p)*4];
                        const ulonglong2 WB = *(const ulonglong2*)&sm->w1sB[(g*128+p)*4];
#pragma unroll
                        for (int r=0;r<8;r++){
                            const ulonglong2 E = *(const ulonglong2*)&sm->esm[jb][rq+r][4*g];
                            acc0[r]=fma2(E.x,WA.x,acc0[r]); acc0[r]=fma2(E.y,WA.y,acc0[r]);
                            acc1[r]=fma2(E.x,WB.x,acc1[r]); acc1[r]=fma2(E.y,WB.y,acc1[r]);
                        }
                    }
                    float qx,qy; unpack2(qv,qx,qy);
#pragma unroll
                    for (int r=0;r<8;r++){
                        int i = rq+r;
                        float d = sm->dbuf[jb][i], a = sm->abuf[jb][i];
                        float px,py; unpack2(pv[r],px,py);
                        float a0x,a0y,a1x,a1y;
                        unpack2(acc0[r],a0x,a0y); unpack2(acc1[r],a1x,a1y);
                        float h0 = a0x+a0y + px + qx + d*w1dx + a*w1ex;
                        float h1 = a1x+a1y + py + qy + d*w1dy + a*w1ey;
                        h0 = silu_f(h0); h1 = silu_f(h1);
                        if (i==j){ h0=0.f; h1=0.f; }
                        *(float2*)&sm->hdn[jb][i][2*p] = make_float2(h0,h1);
                    }
                }
            }
            __syncthreads();

            // ---- [C]: e-update (quarter-column partial + RED), pos scalars, S0 ----
            {
                const int qq  = wrp >> 2;        // 0..3 column quarter
                const int sub = wrp & 3;         // 0..3 stream group
                const float* wtq = g_w2t + l*8192 + lane*4;
                u64 acc[16];
#pragma unroll
                for (int m=0;m<16;m++) acc[m]=0ULL;
#pragma unroll 4
                for (int cc4=0; cc4<16; cc4++){
                    const int c4 = qq*16 + cc4;
                    const ulonglong2 ww = *(const ulonglong2*)&wtq[c4*128];
                    const float* hb = &sm->hdn[0][0][4*c4] + (size_t)sub*16*SD;
#pragma unroll
                    for (int m=0;m<16;m++){
                        const ulonglong2 hv = *(const ulonglong2*)(hb + m*SD);
                        acc[m]=fma2(hv.x,ww.x,acc[m]); acc[m]=fma2(hv.y,ww.y,acc[m]);
                    }
                }
#pragma unroll
                for (int m=0;m<16;m++){
                    int st = sub*16 + m;         // 0..63 = jb*32 + i
                    int jb = st >> 5, i = st & 31;
                    int j = j0 + jb;
                    if (i != j){
                        float ax,ay; unpack2(acc[m],ax,ay);
                        float val = ax + ay + (qq==0 ? b2k : 0.f);
                        int eL = i*31 + j - (j>i);
                        atomicAdd(&g_e[(ebase+eL)*ED + lane], val);
                    }
                }
            }
            // [C1] pos scalars for both js
#pragma unroll
            for (int jb=0; jb<2; jb++){
                float pdx=0.f, pdy=0.f, pdz=0.f;
#pragma unroll
                for (int r=0;r<2;r++){
                    int i = wrp + 16*r;
                    float part = 0.f;
#pragma unroll
                    for (int m=0;m<8;m++)
                        part += sm->hdn[jb][i][lane+32*m] * sm->w2p[lane+32*m];
#pragma unroll
                    for (int off=16; off>0; off>>=1)
                        part += __shfl_xor_sync(0xffffffffu, part, off);
                    if (lane==0){
                        float t = part + b2p;
                        pdx += sm->rnb[jb][i][0]*t;
                        pdy += sm->rnb[jb][i][1]*t;
                        pdz += sm->rnb[jb][i][2]*t;
                    }
                }
                if (lane==0){
                    sm->pdpart[jb][wrp][0]=pdx;
                    sm->pdpart[jb][wrp][1]=pdy;
                    sm->pdpart[jb][wrp][2]=pdz;
                }
            }
            // [C0] S0 rows j0,j1 via column sums
            {
                int jb = tid >> 8;
                int col = tid & 255;
                float s0=0.f, s1=0.f;
#pragma unroll
                for (int i=0;i<32;i+=2){
                    s0 += sm->hdn[jb][i][col];
                    s1 += sm->hdn[jb][i+1][col];
                }
                S0g[(j0+jb)*SD + col] = s0 + s1;
            }
            __syncthreads();
        } // jp

        if (tid<6){
            int sel = tid/3, cc = tid - sel*3;
            float sum=0.f;
#pragma unroll
            for (int w=0;w<16;w++) sum += sm->pdpart[sel][w][cc];
            sm->npos[30+sel][cc] += sum;
        }
        // s += (S0 @ W2s)/31 + b2s
        {
            float acc[HROWS];
#pragma unroll
            for (int r=0;r<HROWS;r++) acc[r]=0.f;
            for (int kg=0; kg<64; kg++){
                float w0=W2[(4*kg+0)*MSG_OUT+c], w1=W2[(4*kg+1)*MSG_OUT+c];
                float w2v=W2[(4*kg+2)*MSG_OUT+c], w3=W2[(4*kg+3)*MSG_OUT+c];
#pragma unroll
                for (int r=0;r<HROWS;r++){
                    const float4 v = __ldg((const float4*)&S0g[(r0+r)*SD + 4*kg]);
                    acc[r] += v.x*w0 + v.y*w1 + v.z*w2v + v.w*w3;
                }
            }
            __syncthreads();  // npos folds done; buffers free
            float b2s = b2[c];
#pragma unroll
            for (int r=0;r<HROWS;r++)
                sg[(r0+r)*SD + c] += acc[r]*(1.f/31.f) + b2s;
        }
        if (tid<96){
            int i = tid/3, cc = tid%3;
            sm->pos[i][cc] += sm->npos[i][cc]*(1.f/31.f);
        }
        __syncthreads();
    } // layers

    // ---------------- atoms + pos out ----------------
    float* Pbuf = sm->w1sA;              // 32KB scratch (w1sA+w1sB contiguous)
    {
        float acc[HROWS];
#pragma unroll
        for (int r=0;r<HROWS;r++) acc[r]=0.f;
        for (int kg=0; kg<64; kg++){
            float w0=Wh1[(4*kg+0)*SD+c], w1=Wh1[(4*kg+1)*SD+c];
            float w2v=Wh1[(4*kg+2)*SD+c], w3=Wh1[(4*kg+3)*SD+c];
#pragma unroll
            for (int r=0;r<HROWS;r++){
                const float4 v = __ldg((const float4*)&sg[(r0+r)*SD + 4*kg]);
                acc[r] += v.x*w0 + v.y*w1 + v.z*w2v + v.w*w3;
            }
        }
        float bb = bh1[c];
#pragma unroll
        for (int r=0;r<HROWS;r++) Pbuf[(r0+r)*SD + c] = silu_f(acc[r]+bb);
    }
    __syncthreads();
    for (int o = tid; o < NPER*16; o += NT){
        int i = o>>4, cc = o&15;
        float a = bh2[cc];
        for (int k=0;k<SD;k++) a += Pbuf[i*SD + k]*Wh2[k*16+cc];
        outA[(nodeBase+i)*16+cc] = a;
    }
    if (tid < 96){
        int i = tid/3, cc = tid%3;
        outP[(nodeBase+i)*3+cc] = sm->pos[i][cc];
    }
    __syncthreads();

    // ---------------- bonds ----------------
    float* hdnf = &sm->hdn[0][0][0];
    float* bP = hdnf;                    // 32 x 128
    {
        const int c128 = tid & 127;
        const int grp  = tid >> 7;
        float acc[8];
#pragma unroll
        for (int r=0;r<8;r++) acc[r]=0.f;
        for (int kg=0; kg<64; kg++){
            float w0=We1[(4*kg+0)*128+c128], w1=We1[(4*kg+1)*128+c128];
            float w2v=We1[(4*kg+2)*128+c128], w3=We1[(4*kg+3)*128+c128];
#pragma unroll
            for (int r=0;r<8;r++){
                const float4 v = __ldg((const float4*)&sg[(grp*8+r)*SD + 4*kg]);
                acc[r] += v.x*w0 + v.y*w1 + v.z*w2v + v.w*w3;
            }
        }
#pragma unroll
        for (int r=0;r<8;r++) bP[(grp*8+r)*128 + c128] = acc[r];
    }
    float* We1e_s = hdnf + 16*SD;        // 32 x 128
    for (int idx = tid; idx < 32*128; idx += NT)
        We1e_s[idx] = We1[(256 + (idx>>7))*128 + (idx&127)];
    __syncthreads();

    float* bh = &sm->hdn[1][0][0];       // 16 x 128
    float* ebuf = &sm->esm[0][0][0];     // 16 x 32
    {
        const int c128 = tid & 127;
        const int grp  = tid >> 7;
        const float w288 = We1[288*128 + c128];
        const float bbe  = be1[c128];
        for (int pblk=0; pblk<62; pblk++){
            if (tid < 128){              // 128 float4 = 16 rows x 8 f4
                int q = tid >> 3, k4 = tid & 7;
                int eL = pblk*16 + q;
                *(float4*)&ebuf[q*32 + 4*k4] =
                    *(const float4*)&g_e[(ebase+eL)*ED + 4*k4];
            }
            if (tid < 16){
                int eL = pblk*16 + tid;
                int i = eL/31, jj = eL - i*31; int j = jj + (jj>=i);
                float rx=sm->pos[j][0]-sm->pos[i][0];
                float ry=sm->pos[j][1]-sm->pos[i][1];
                float rz=sm->pos[j][2]-sm->pos[i][2];
                sm->dbuf[0][tid] = sqrtf(fmaxf(rx*rx+ry*ry+rz*rz, 1e-6f));
            }
            __syncthreads();
#pragma unroll
            for (int qq=0; qq<4; qq++){
                int q = grp*4 + qq;
                int eL = pblk*16 + q;
                int i = eL/31, jj = eL - i*31; int j = jj + (jj>=i);
                float a = bbe + bP[i*128+c128] + bP[j*128+c128] + sm->dbuf[0][q]*w288;
#pragma unroll
                for (int kg=0; kg<8; kg++){
                    float4 e4 = ((const float4*)&ebuf[q*32])[kg];
                    a += e4.x*We1e_s[(4*kg+0)*128+c128] + e4.y*We1e_s[(4*kg+1)*128+c128]
                       + e4.z*We1e_s[(4*kg+2)*128+c128] + e4.w*We1e_s[(4*kg+3)*128+c128];
                }
                bh[q*128+c128] = silu_f(a);
            }
            __syncthreads();
            {
                int qq = wrp;
                int eL = pblk*16 + qq;
#pragma unroll
                for (int b=0;b<5;b++){
                    float part = 0.f;
#pragma unroll
                    for (int m=0;m<4;m++){
                        int cc = lane + 32*m;
                        part += bh[qq*128+cc] * We2[cc*5+b];
                    }
#pragma unroll
                    for (int off=16; off>0; off>>=1)
                        part += __shfl_xor_sync(0xffffffffu, part, off);
                    if (lane==0) outB[(ebase+eL)*5+b] = part + be2[b];
                }
            }
            __syncthreads();
        }
    }
}

extern "C" void kernel_launch(void* const* d_in, const int* in_sizes, int n_in,
                              void* d_out, int out_size)
{
    const float* x    = (const float*)d_in[0];
    const float* z    = (const float*)d_in[1];
    const float* rot  = (const float*)d_in[2];
    const float* eattr= (const float*)d_in[4];
    const float* Wam  = (const float*)d_in[6];
    const float* bam  = (const float*)d_in[7];
    const float* Wbm  = (const float*)d_in[8];
    const float* bbm  = (const float*)d_in[9];
    const float* gW1  = (const float*)d_in[10];
    const float* gb1  = (const float*)d_in[11];
    const float* gW2  = (const float*)d_in[12];
    const float* gb2  = (const float*)d_in[13];
    const float* Wh1  = (const float*)d_in[14];
    const float* bh1  = (const float*)d_in[15];
    const float* Wh2  = (const float*)d_in[16];
    const float* bh2  = (const float*)d_in[17];
    const float* We1  = (const float*)d_in[18];
    const float* be1  = (const float*)d_in[19];
    const float* We2  = (const float*)d_in[20];
    const float* be2  = (const float*)d_in[21];

    float* out  = (float*)d_out;
    float* outA = out;
    float* outB = out + (size_t)NNODE*16;
    float* outP = out + (size_t)NNODE*16 + (size_t)ETOT*5;

    prep_kernel<<<320, 256>>>(gW2, gW1);

    const size_t shmem = sizeof(SM);
    cudaFuncSetAttribute(dec_kernel, cudaFuncAttributeMaxDynamicSharedMemorySize, (int)shmem);
    dec_kernel<<<NMOL, NT, shmem>>>(x,z,rot,eattr,Wam,bam,Wbm,bbm,
                                    gW1,gb1,gW2,gb2,Wh1,bh1,Wh2,bh2,
                                    We1,be1,We2,be2,outA,outB,outP);
}